// round 7
// baseline (speedup 1.0000x reference)
#include <cuda_runtime.h>
#include <math.h>

#define BB 64
#define LZ 128
#define EE 512
#define HH 512
#define VV 32000
#define TT 64
#define NVBLK 500            // logits blocks (64 v each)
#define KCH 32               // k-chunk size
#define NCHUNK (EE / KCH)    // 16

typedef unsigned long long ull;

// ---------------- device scratch ----------------
__device__ float g_hT[2][HH * BB];        // hidden state, k-major [k][b], double buffered
__device__ float g_xT[EE * BB];           // input x for t=0 only, k-major [k][b]
__device__ float g_WfcT[(size_t)EE * VV]; // W_fc transposed [k][v]
__device__ ull   g_amax[2][BB];           // packed argmax keys, double buffered

// ---------------- helpers ----------------
__device__ __forceinline__ void fma2(ull& d, ull a, ull b) {
    asm("fma.rn.f32x2 %0, %1, %2, %0;" : "+l"(d) : "l"(a), "l"(b));
}
__device__ __forceinline__ void cp_async16(void* smem, const void* gmem) {
    unsigned s = (unsigned)__cvta_generic_to_shared(smem);
    asm volatile("cp.async.cg.shared.global [%0], [%1], 16;\n" :: "r"(s), "l"(gmem));
}
__device__ __forceinline__ void cp_commit() {
    asm volatile("cp.async.commit_group;\n");
}
__device__ __forceinline__ void sts_dup(unsigned saddr, float f) {
    asm volatile("st.shared.v2.f32 [%0], {%1, %1};\n" :: "r"(saddr), "f"(f));
}
// monotone float->uint mapping (order preserved)
__device__ __forceinline__ unsigned ford(float f) {
    unsigned u = __float_as_uint(f);
    return (u & 0x80000000u) ? ~u : (u | 0x80000000u);
}

// ---------------- init: h0 = z @ W_proj^T + b_proj ----------------
__global__ void init_h_kernel(const float* __restrict__ z,
                              const float* __restrict__ Wp,
                              const float* __restrict__ bp) {
    int b = threadIdx.x;
    int j = blockIdx.x * 4 + threadIdx.y;
    float acc = 0.f;
    const float* zr = z + b * LZ;
    const float* wr = Wp + j * LZ;
#pragma unroll 4
    for (int l = 0; l < LZ; l++) acc += zr[l] * wr[l];
    acc += bp[j];
    g_hT[0][j * BB + b] = acc;
    g_xT[j * BB + b]    = acc;
}

// ---------------- transpose W_fc [V][K] -> g_WfcT [K][V] ----------------
__global__ void transpose_wfc_kernel(const float* __restrict__ Wfc) {
    __shared__ float tile[32][33];
    int v0 = blockIdx.x * 32;
    int k0 = blockIdx.y * 32;
    int tx = threadIdx.x, ty = threadIdx.y;
#pragma unroll
    for (int i = ty; i < 32; i += 8)
        tile[i][tx] = Wfc[(size_t)(v0 + i) * EE + (k0 + tx)];
    __syncthreads();
#pragma unroll
    for (int i = ty; i < 32; i += 8)
        g_WfcT[(size_t)(k0 + i) * VV + (v0 + tx)] = tile[tx][i];
}

// ---------------- GRU cell, 8-way k-split, embedded-gather x ----------------
// block (32 bp, 8 ks) = 256 threads, grid 512 -> one j per block.
// t==0: x from g_xT. t>0: x gathered directly from emb via g_amax[(t-1)&1].
// Also resets g_amax[t&1] (buffer logits(t) will atomically fill).
__global__ void __launch_bounds__(256) gru_kernel(const float* __restrict__ emb,
                                                  const float* __restrict__ Wih,
                                                  const float* __restrict__ bih,
                                                  const float* __restrict__ Whh,
                                                  const float* __restrict__ bhh,
                                                  int t, int cur) {
    int bp = threadIdx.x;                 // 0..31
    int ks = threadIdx.y;                 // 0..7 (k slice of 64)
    int j  = blockIdx.x;                  // 0..511
    int tid = ks * 32 + bp;

    // reset next argmax buffer (block 0 only; safe: logits(t) runs after this kernel)
    if (blockIdx.x == 0 && tid < BB) g_amax[t & 1][tid] = 0ull;

    // resolve x source
    const float* xp0;
    const float* xp1;
    int xstride;
    if (t > 0) {
        ull k0 = g_amax[(t - 1) & 1][2 * bp];
        ull k1 = g_amax[(t - 1) & 1][2 * bp + 1];
        unsigned id0 = ~(unsigned)k0;
        unsigned id1 = ~(unsigned)k1;
        xp0 = emb + (size_t)id0 * EE + ks * 64;
        xp1 = emb + (size_t)id1 * EE + ks * 64;
        xstride = 1;
    } else {
        xp0 = g_xT + (size_t)(ks * 64) * BB + 2 * bp;
        xp1 = xp0 + 1;
        xstride = BB;
    }

    const float4* wri = (const float4*)(Wih + (size_t)j * EE) + ks * 16;
    const float4* wzi = (const float4*)(Wih + (size_t)(j + HH) * EE) + ks * 16;
    const float4* wni = (const float4*)(Wih + (size_t)(j + 2 * HH) * EE) + ks * 16;
    const float4* wrh = (const float4*)(Whh + (size_t)j * HH) + ks * 16;
    const float4* wzh = (const float4*)(Whh + (size_t)(j + HH) * HH) + ks * 16;
    const float4* wnh = (const float4*)(Whh + (size_t)(j + 2 * HH) * HH) + ks * 16;

    const float* hcol = g_hT[cur] + 2 * bp + (size_t)(ks * 64) * BB;

    float air0 = 0.f, air1 = 0.f, aiz0 = 0.f, aiz1 = 0.f, ain0 = 0.f, ain1 = 0.f;
    float ahr0 = 0.f, ahr1 = 0.f, ahz0 = 0.f, ahz1 = 0.f, ahn0 = 0.f, ahn1 = 0.f;

#pragma unroll 2
    for (int k4 = 0; k4 < 16; k4++) {
        float4 wa = wri[k4], wb = wzi[k4], wc = wni[k4];
        float4 wd = wrh[k4], we = wzh[k4], wf = wnh[k4];
#pragma unroll
        for (int s = 0; s < 4; s++) {
            int k = k4 * 4 + s;
            float x0 = xp0[k * xstride];
            float x1 = xp1[k * xstride];
            float2 h2 = *(const float2*)(hcol + (size_t)k * BB);
            float wA = ((const float*)&wa)[s];
            float wB = ((const float*)&wb)[s];
            float wC = ((const float*)&wc)[s];
            float wD = ((const float*)&wd)[s];
            float wE = ((const float*)&we)[s];
            float wF = ((const float*)&wf)[s];
            air0 += wA * x0; air1 += wA * x1;
            aiz0 += wB * x0; aiz1 += wB * x1;
            ain0 += wC * x0; ain1 += wC * x1;
            ahr0 += wD * h2.x; ahr1 += wD * h2.y;
            ahz0 += wE * h2.x; ahz1 += wE * h2.y;
            ahn0 += wF * h2.x; ahn1 += wF * h2.y;
        }
    }

    __shared__ float2 sred[8][6][32];
    sred[ks][0][bp] = make_float2(air0, air1);
    sred[ks][1][bp] = make_float2(aiz0, aiz1);
    sred[ks][2][bp] = make_float2(ain0, ain1);
    sred[ks][3][bp] = make_float2(ahr0, ahr1);
    sred[ks][4][bp] = make_float2(ahz0, ahz1);
    sred[ks][5][bp] = make_float2(ahn0, ahn1);
    __syncthreads();

    if (ks == 0) {
        float g[6][2];
#pragma unroll
        for (int gi = 0; gi < 6; gi++) {
            float a0 = 0.f, a1 = 0.f;
#pragma unroll
            for (int s = 0; s < 8; s++) {
                float2 sv = sred[s][gi][bp];
                a0 += sv.x; a1 += sv.y;
            }
            g[gi][0] = a0; g[gi][1] = a1;
        }

        float bir = bih[j], biz = bih[j + HH], bin = bih[j + 2 * HH];
        float bhr = bhh[j], bhz = bhh[j + HH], bhn = bhh[j + 2 * HH];

        float2 hprev = *(const float2*)(g_hT[cur] + (size_t)j * BB + 2 * bp);
        float* hout = g_hT[1 - cur] + (size_t)j * BB + 2 * bp;

        {
            float r  = 1.f / (1.f + expf(-((g[0][0] + bir) + (g[3][0] + bhr))));
            float zg = 1.f / (1.f + expf(-((g[1][0] + biz) + (g[4][0] + bhz))));
            float n  = tanhf((g[2][0] + bin) + r * (g[5][0] + bhn));
            hout[0]  = (1.f - zg) * n + zg * hprev.x;
        }
        {
            float r  = 1.f / (1.f + expf(-((g[0][1] + bir) + (g[3][1] + bhr))));
            float zg = 1.f / (1.f + expf(-((g[1][1] + biz) + (g[4][1] + bhz))));
            float n  = tanhf((g[2][1] + bin) + r * (g[5][1] + bhn));
            hout[1]  = (1.f - zg) * n + zg * hprev.y;
        }
    }
}

// ---------------- logits + fused atomic argmax ----------------
// grid 500 (64 v per block), block 128 = 8 vg x 16 bg, tile 8v x 4b.
// W double-buffered via cp.async (v-paired f32x2 operands, no dup movs);
// h pre-duplicated into shared once per chunk.
__global__ void __launch_bounds__(128, 4) logits_kernel(const float* __restrict__ bfc,
                                                        float* __restrict__ out,
                                                        int t, int hbuf) {
    __shared__ __align__(16) float sW[2][KCH * 64];  // 8 KB x2
    __shared__ __align__(16) ull   sHd[KCH * 64];    // 16 KB (h duplicated)

    int tid = threadIdx.x;
    int vg = tid & 7;          // 0..7   (8 v each)
    int bg = tid >> 3;         // 0..15  (4 batches each)
    int v0 = blockIdx.x * 64;
    int vA = v0 + vg * 8;

    const float* hbase = g_hT[hbuf];
    unsigned sHd_base = (unsigned)__cvta_generic_to_shared(sHd);

    // W chunk: 32kk x 64v = 2048 floats = 512 x 16B; 4 cp.async per thread
    auto issueW = [&](int c, int buf) {
        int kc = c * KCH;
#pragma unroll
        for (int p = 0; p < 4; p++) {
            int linear = tid + p * 128;       // 0..511
            int kk = linear >> 4;
            int sub = linear & 15;
            cp_async16(&sW[buf][kk * 64 + sub * 4],
                       &g_WfcT[(size_t)(kc + kk) * VV + v0 + sub * 4]);
        }
        cp_commit();
    };

    float hreg[16];
    auto loadH = [&](int c) {
#pragma unroll
        for (int r = 0; r < 16; r++)
            hreg[r] = hbase[(size_t)(c * KCH + 2 * r + (tid >> 6)) * BB + (tid & 63)];
    };

    ull acc[4][4];   // [vpair][batch]
#pragma unroll
    for (int vp = 0; vp < 4; vp++)
#pragma unroll
        for (int b = 0; b < 4; b++) acc[vp][b] = 0ull;

    issueW(0, 0);
    issueW(1, 1);
    loadH(0);

#pragma unroll 1
    for (int c = 0; c < NCHUNK; c++) {
        if (c < NCHUNK - 1) asm volatile("cp.async.wait_group 1;\n");
        else                asm volatile("cp.async.wait_group 0;\n");
        __syncthreads();   // W[c] visible; all threads done with sHd from c-1

        // duplicate h chunk c into sHd
#pragma unroll
        for (int r = 0; r < 16; r++)
            sts_dup(sHd_base + (unsigned)((r * 128 + tid) * 8), hreg[r]);
        __syncthreads();   // sHd ready

        if (c + 1 < NCHUNK) loadH(c + 1);

        const float* Wb = sW[c & 1];
#pragma unroll 4
        for (int kk = 0; kk < KCH; kk++) {
            float4 w0 = *(const float4*)(Wb + kk * 64 + vg * 8);
            float4 w1 = *(const float4*)(Wb + kk * 64 + vg * 8 + 4);
            ull W01 = ((const ull*)&w0)[0];   // (vA, vA+1)
            ull W23 = ((const ull*)&w0)[1];   // (vA+2, vA+3)
            ull W45 = ((const ull*)&w1)[0];
            ull W67 = ((const ull*)&w1)[1];
            const ulonglong2* hp = (const ulonglong2*)&sHd[kk * 64 + bg * 4];
            ulonglong2 hA = hp[0];            // b0,b1 duplicated
            ulonglong2 hB = hp[1];            // b2,b3

            fma2(acc[0][0], W01, hA.x); fma2(acc[0][1], W01, hA.y);
            fma2(acc[0][2], W01, hB.x); fma2(acc[0][3], W01, hB.y);
            fma2(acc[1][0], W23, hA.x); fma2(acc[1][1], W23, hA.y);
            fma2(acc[1][2], W23, hB.x); fma2(acc[1][3], W23, hB.y);
            fma2(acc[2][0], W45, hA.x); fma2(acc[2][1], W45, hA.y);
            fma2(acc[2][2], W45, hB.x); fma2(acc[2][3], W45, hB.y);
            fma2(acc[3][0], W67, hA.x); fma2(acc[3][1], W67, hA.y);
            fma2(acc[3][2], W67, hB.x); fma2(acc[3][3], W67, hB.y);
        }

        __syncthreads();   // done with sW[c&1]
        if (c + 2 < NCHUNK) issueW(c + 2, c & 1);
    }

    float4 biasLo = *(const float4*)&bfc[vA];
    float4 biasHi = *(const float4*)&bfc[vA + 4];

    ull* amax = g_amax[t & 1];

#pragma unroll
    for (int i = 0; i < 4; i++) {
        int b = bg * 4 + i;
        float2 a0 = *(float2*)&acc[0][i];
        float2 a1 = *(float2*)&acc[1][i];
        float2 a2 = *(float2*)&acc[2][i];
        float2 a3 = *(float2*)&acc[3][i];

        float4 olo = make_float4(a0.x + biasLo.x, a0.y + biasLo.y,
                                 a1.x + biasLo.z, a1.y + biasLo.w);
        float4 ohi = make_float4(a2.x + biasHi.x, a2.y + biasHi.y,
                                 a3.x + biasHi.z, a3.y + biasHi.w);

        size_t rowoff = ((size_t)b * TT + t) * VV;
        __stcs((float4*)(out + rowoff + vA), olo);
        __stcs((float4*)(out + rowoff + vA + 4), ohi);

        // local argmax over 8 v (ascending, strict > keeps first-max)
        float best = olo.x; int bidx = vA;
        if (olo.y > best) { best = olo.y; bidx = vA + 1; }
        if (olo.z > best) { best = olo.z; bidx = vA + 2; }
        if (olo.w > best) { best = olo.w; bidx = vA + 3; }
        if (ohi.x > best) { best = ohi.x; bidx = vA + 4; }
        if (ohi.y > best) { best = ohi.y; bidx = vA + 5; }
        if (ohi.z > best) { best = ohi.z; bidx = vA + 6; }
        if (ohi.w > best) { best = ohi.w; bidx = vA + 7; }

        // reduce across 8 vg lanes sharing this bg (xor bits 0..2 stay in-group)
#pragma unroll
        for (int m = 1; m < 8; m <<= 1) {
            float ov = __shfl_xor_sync(0xffffffffu, best, m);
            int   oi = __shfl_xor_sync(0xffffffffu, bidx, m);
            if (ov > best || (ov == best && oi < bidx)) { best = ov; bidx = oi; }
        }
        if (vg == 0) {
            ull key = ((ull)ford(best) << 32) | (ull)(~(unsigned)bidx);
            atomicMax(&amax[b], key);
        }
    }
}

// ---------------- launch ----------------
extern "C" void kernel_launch(void* const* d_in, const int* in_sizes, int n_in,
                              void* d_out, int out_size) {
    const float* z     = (const float*)d_in[0];
    const float* emb   = (const float*)d_in[1];
    const float* Wproj = (const float*)d_in[2];
    const float* bproj = (const float*)d_in[3];
    const float* Wih   = (const float*)d_in[4];
    const float* bih   = (const float*)d_in[5];
    const float* Whh   = (const float*)d_in[6];
    const float* bhh   = (const float*)d_in[7];
    const float* Wfc   = (const float*)d_in[8];
    const float* bfc   = (const float*)d_in[9];
    float* out = (float*)d_out;

    init_h_kernel<<<128, dim3(64, 4)>>>(z, Wproj, bproj);
    transpose_wfc_kernel<<<dim3(VV / 32, EE / 32), dim3(32, 8)>>>(Wfc);

    int cur = 0;
    for (int t = 0; t < TT; t++) {
        gru_kernel<<<512, dim3(32, 8)>>>(emb, Wih, bih, Whh, bhh, t, cur);
        logits_kernel<<<NVBLK, 128>>>(bfc, out, t, 1 - cur);
        cur = 1 - cur;
    }
}

// round 8
// speedup vs baseline: 2.4925x; 2.4925x over previous
#include <cuda_runtime.h>
#include <math.h>

#define BB 64
#define LZ 128
#define EE 512
#define HH 512
#define VV 32000
#define TT 64
#define NVBLK 500            // logits blocks (64 v each)
#define KCH 32               // k-chunk size
#define NCHUNK (EE / KCH)    // 16

typedef unsigned long long ull;

// ---------------- device scratch ----------------
__device__ float g_hT[2][HH * BB];        // hidden state, k-major [k][b], double buffered
__device__ float g_xT[EE * BB];           // input x, k-major [k][b]
__device__ float g_WfcT[(size_t)EE * VV]; // W_fc transposed [k][v]
__device__ float2 g_pmax[BB][NVBLK];      // per-(batch, block) partial argmax

// ---------------- helpers ----------------
__device__ __forceinline__ void fma2(ull& d, ull a, ull b) {
    asm("fma.rn.f32x2 %0, %1, %2, %0;" : "+l"(d) : "l"(a), "l"(b));
}
__device__ __forceinline__ ull dup2(float a) {
    ull r;
    asm("mov.b64 %0, {%1, %2};" : "=l"(r) : "f"(a), "f"(a));
    return r;
}
__device__ __forceinline__ void cp_async16(void* smem, const void* gmem) {
    unsigned s = (unsigned)__cvta_generic_to_shared(smem);
    asm volatile("cp.async.cg.shared.global [%0], [%1], 16;\n" :: "r"(s), "l"(gmem));
}
__device__ __forceinline__ void cp_commit() {
    asm volatile("cp.async.commit_group;\n");
}

// ---------------- init: h0 = z @ W_proj^T + b_proj ----------------
__global__ void init_h_kernel(const float* __restrict__ z,
                              const float* __restrict__ Wp,
                              const float* __restrict__ bp) {
    int b = threadIdx.x;
    int j = blockIdx.x * 4 + threadIdx.y;
    float acc = 0.f;
    const float* zr = z + b * LZ;
    const float* wr = Wp + j * LZ;
#pragma unroll 4
    for (int l = 0; l < LZ; l++) acc += zr[l] * wr[l];
    acc += bp[j];
    g_hT[0][j * BB + b] = acc;
    g_xT[j * BB + b]    = acc;
}

// ---------------- transpose W_fc [V][K] -> g_WfcT [K][V] ----------------
__global__ void transpose_wfc_kernel(const float* __restrict__ Wfc) {
    __shared__ float tile[32][33];
    int v0 = blockIdx.x * 32;
    int k0 = blockIdx.y * 32;
    int tx = threadIdx.x, ty = threadIdx.y;
#pragma unroll
    for (int i = ty; i < 32; i += 8)
        tile[i][tx] = Wfc[(size_t)(v0 + i) * EE + (k0 + tx)];
    __syncthreads();
#pragma unroll
    for (int i = ty; i < 32; i += 8)
        g_WfcT[(size_t)(k0 + i) * VV + (v0 + tx)] = tile[tx][i];
}

// ---------------- GRU cell, 8-way k-split ----------------
// block (32 bp, 8 ks) = 256 threads, grid 512 -> one j per block
__global__ void __launch_bounds__(256) gru_kernel(const float* __restrict__ Wih,
                                                  const float* __restrict__ bih,
                                                  const float* __restrict__ Whh,
                                                  const float* __restrict__ bhh,
                                                  int cur) {
    int bp = threadIdx.x;                 // 0..31
    int ks = threadIdx.y;                 // 0..7 (k slice of 64)
    int j  = blockIdx.x;                  // 0..511

    const float4* wri = (const float4*)(Wih + (size_t)j * EE) + ks * 16;
    const float4* wzi = (const float4*)(Wih + (size_t)(j + HH) * EE) + ks * 16;
    const float4* wni = (const float4*)(Wih + (size_t)(j + 2 * HH) * EE) + ks * 16;
    const float4* wrh = (const float4*)(Whh + (size_t)j * HH) + ks * 16;
    const float4* wzh = (const float4*)(Whh + (size_t)(j + HH) * HH) + ks * 16;
    const float4* wnh = (const float4*)(Whh + (size_t)(j + 2 * HH) * HH) + ks * 16;

    const float* xcol = g_xT + 2 * bp + (size_t)(ks * 64) * BB;
    const float* hcol = g_hT[cur] + 2 * bp + (size_t)(ks * 64) * BB;

    float air0 = 0.f, air1 = 0.f, aiz0 = 0.f, aiz1 = 0.f, ain0 = 0.f, ain1 = 0.f;
    float ahr0 = 0.f, ahr1 = 0.f, ahz0 = 0.f, ahz1 = 0.f, ahn0 = 0.f, ahn1 = 0.f;

#pragma unroll 2
    for (int k4 = 0; k4 < 16; k4++) {
        float4 wa = wri[k4], wb = wzi[k4], wc = wni[k4];
        float4 wd = wrh[k4], we = wzh[k4], wf = wnh[k4];
#pragma unroll
        for (int s = 0; s < 4; s++) {
            int k = k4 * 4 + s;
            float2 x2 = *(const float2*)(xcol + (size_t)k * BB);
            float2 h2 = *(const float2*)(hcol + (size_t)k * BB);
            float wA = ((const float*)&wa)[s];
            float wB = ((const float*)&wb)[s];
            float wC = ((const float*)&wc)[s];
            float wD = ((const float*)&wd)[s];
            float wE = ((const float*)&we)[s];
            float wF = ((const float*)&wf)[s];
            air0 += wA * x2.x; air1 += wA * x2.y;
            aiz0 += wB * x2.x; aiz1 += wB * x2.y;
            ain0 += wC * x2.x; ain1 += wC * x2.y;
            ahr0 += wD * h2.x; ahr1 += wD * h2.y;
            ahz0 += wE * h2.x; ahz1 += wE * h2.y;
            ahn0 += wF * h2.x; ahn1 += wF * h2.y;
        }
    }

    __shared__ float2 sred[8][6][32];
    sred[ks][0][bp] = make_float2(air0, air1);
    sred[ks][1][bp] = make_float2(aiz0, aiz1);
    sred[ks][2][bp] = make_float2(ain0, ain1);
    sred[ks][3][bp] = make_float2(ahr0, ahr1);
    sred[ks][4][bp] = make_float2(ahz0, ahz1);
    sred[ks][5][bp] = make_float2(ahn0, ahn1);
    __syncthreads();

    if (ks == 0) {
        float g[6][2];
#pragma unroll
        for (int gi = 0; gi < 6; gi++) {
            float a0 = 0.f, a1 = 0.f;
#pragma unroll
            for (int s = 0; s < 8; s++) {
                float2 sv = sred[s][gi][bp];
                a0 += sv.x; a1 += sv.y;
            }
            g[gi][0] = a0; g[gi][1] = a1;
        }

        float bir = bih[j], biz = bih[j + HH], bin = bih[j + 2 * HH];
        float bhr = bhh[j], bhz = bhh[j + HH], bhn = bhh[j + 2 * HH];

        float2 hprev = *(const float2*)(g_hT[cur] + (size_t)j * BB + 2 * bp);
        float* hout = g_hT[1 - cur] + (size_t)j * BB + 2 * bp;

        {
            float r  = 1.f / (1.f + expf(-((g[0][0] + bir) + (g[3][0] + bhr))));
            float zg = 1.f / (1.f + expf(-((g[1][0] + biz) + (g[4][0] + bhz))));
            float n  = tanhf((g[2][0] + bin) + r * (g[5][0] + bhn));
            hout[0]  = (1.f - zg) * n + zg * hprev.x;
        }
        {
            float r  = 1.f / (1.f + expf(-((g[0][1] + bir) + (g[3][1] + bhr))));
            float zg = 1.f / (1.f + expf(-((g[1][1] + biz) + (g[4][1] + bhz))));
            float n  = tanhf((g[2][1] + bin) + r * (g[5][1] + bhn));
            hout[1]  = (1.f - zg) * n + zg * hprev.y;
        }
    }
}

// ---------------- logits + fused partial argmax (cp.async pipelined) -------
// grid 500 (64 v per block), block 128 = 16 vg x 8 bg, tile 4v x 8b.
// 16 chunks of 32 kk; W and h chunks double-buffered in shared via cp.async.
// (Proven 49.4us configuration from Round 4.)
__global__ void __launch_bounds__(128, 4) logits_kernel(const float* __restrict__ bfc,
                                                        float* __restrict__ out,
                                                        int t, int hbuf) {
    __shared__ __align__(16) float sW[2][KCH * 64];  // 8 KB each
    __shared__ __align__(16) float sH[2][KCH * 64];  // 8 KB each

    int tid = threadIdx.x;
    int vg = tid & 15;
    int bg = tid >> 4;
    int v0 = blockIdx.x * 64;
    int vA = v0 + vg * 4;

    const float* hbase = g_hT[hbuf];

    auto issue_chunk = [&](int c, int buf) {
        int kc = c * KCH;
#pragma unroll
        for (int p = 0; p < 4; p++) {
            int linear = tid + p * 128;          // 0..511
            int kk = linear >> 4;
            int sub = linear & 15;
            cp_async16(&sW[buf][kk * 64 + sub * 4],
                       &g_WfcT[(size_t)(kc + kk) * VV + v0 + sub * 4]);
        }
#pragma unroll
        for (int p = 0; p < 4; p++) {
            int linear = tid + p * 128;
            int kk = linear >> 4;
            int sub = linear & 15;
            cp_async16(&sH[buf][kk * 64 + sub * 4],
                       &hbase[(size_t)(kc + kk) * BB + sub * 4]);
        }
        cp_commit();
    };

    ull acc[4][4];
#pragma unroll
    for (int v = 0; v < 4; v++)
#pragma unroll
        for (int p = 0; p < 4; p++) acc[v][p] = 0ull;

    issue_chunk(0, 0);
    issue_chunk(1, 1);

#pragma unroll 1
    for (int c = 0; c < NCHUNK; c++) {
        if (c < NCHUNK - 1) asm volatile("cp.async.wait_group 1;\n");
        else                asm volatile("cp.async.wait_group 0;\n");
        __syncthreads();

        const float* Wb = sW[c & 1];
        const float* Hb = sH[c & 1];

#pragma unroll
        for (int kk = 0; kk < KCH; kk++) {
            float4 w = *(const float4*)(Wb + kk * 64 + vg * 4);
            ulonglong2 h01 = *(const ulonglong2*)(Hb + kk * 64 + bg * 8);
            ulonglong2 h23 = *(const ulonglong2*)(Hb + kk * 64 + bg * 8 + 4);

            ull W0 = dup2(w.x), W1 = dup2(w.y), W2 = dup2(w.z), W3 = dup2(w.w);
            fma2(acc[0][0], W0, h01.x); fma2(acc[0][1], W0, h01.y);
            fma2(acc[0][2], W0, h23.x); fma2(acc[0][3], W0, h23.y);
            fma2(acc[1][0], W1, h01.x); fma2(acc[1][1], W1, h01.y);
            fma2(acc[1][2], W1, h23.x); fma2(acc[1][3], W1, h23.y);
            fma2(acc[2][0], W2, h01.x); fma2(acc[2][1], W2, h01.y);
            fma2(acc[2][2], W2, h23.x); fma2(acc[2][3], W2, h23.y);
            fma2(acc[3][0], W3, h01.x); fma2(acc[3][1], W3, h01.y);
            fma2(acc[3][2], W3, h23.x); fma2(acc[3][3], W3, h23.y);
        }

        __syncthreads();                 // everyone done with buffer (c&1)
        if (c + 2 < NCHUNK) issue_chunk(c + 2, c & 1);
    }

    float4 bias = *(const float4*)&bfc[vA];

#pragma unroll
    for (int i = 0; i < 8; i++) {
        int b = bg * 8 + i;
        int p = i >> 1, cc = i & 1;

        float4 o;
        o.x = ((const float*)&acc[0][p])[cc] + bias.x;
        o.y = ((const float*)&acc[1][p])[cc] + bias.y;
        o.z = ((const float*)&acc[2][p])[cc] + bias.z;
        o.w = ((const float*)&acc[3][p])[cc] + bias.w;

        size_t rowoff = ((size_t)b * TT + t) * VV;
        __stcs((float4*)(out + rowoff + vA), o);

        float best = o.x; int bidx = vA;
        if (o.y > best) { best = o.y; bidx = vA + 1; }
        if (o.z > best) { best = o.z; bidx = vA + 2; }
        if (o.w > best) { best = o.w; bidx = vA + 3; }

#pragma unroll
        for (int m = 1; m < 16; m <<= 1) {
            float ov = __shfl_xor_sync(0xffffffffu, best, m);
            int   oi = __shfl_xor_sync(0xffffffffu, bidx, m);
            if (ov > best || (ov == best && oi < bidx)) { best = ov; bidx = oi; }
        }
        if (vg == 0)
            g_pmax[b][blockIdx.x] = make_float2(best, __int_as_float(bidx));
    }
}

// ---------------- final argmax + embedding gather ----------------
// grid 64 (one block per batch), block 128. Coalesced emb row read.
__global__ void argmax_embed_kernel(const float* __restrict__ emb) {
    int b = blockIdx.x;
    int tid = threadIdx.x;

    float best = -3.4e38f;
    int bidx = 0x7fffffff;
    for (int i = tid; i < NVBLK; i += 128) {
        float2 p = g_pmax[b][i];
        float v = p.x;
        int idx = __float_as_int(p.y);
        if (v > best || (v == best && idx < bidx)) { best = v; bidx = idx; }
    }

    __shared__ float sv[128];
    __shared__ int   si[128];
    sv[tid] = best; si[tid] = bidx;
    __syncthreads();
#pragma unroll
    for (int s = 64; s > 0; s >>= 1) {
        if (tid < s) {
            float ov = sv[tid + s]; int oi = si[tid + s];
            if (ov > sv[tid] || (ov == sv[tid] && oi < si[tid])) { sv[tid] = ov; si[tid] = oi; }
        }
        __syncthreads();
    }
    int id = si[0];

    const float* er = emb + (size_t)id * EE;
    for (int k = tid; k < EE; k += 128) g_xT[(size_t)k * BB + b] = er[k];
}

// ---------------- launch ----------------
extern "C" void kernel_launch(void* const* d_in, const int* in_sizes, int n_in,
                              void* d_out, int out_size) {
    const float* z     = (const float*)d_in[0];
    const float* emb   = (const float*)d_in[1];
    const float* Wproj = (const float*)d_in[2];
    const float* bproj = (const float*)d_in[3];
    const float* Wih   = (const float*)d_in[4];
    const float* bih   = (const float*)d_in[5];
    const float* Whh   = (const float*)d_in[6];
    const float* bhh   = (const float*)d_in[7];
    const float* Wfc   = (const float*)d_in[8];
    const float* bfc   = (const float*)d_in[9];
    float* out = (float*)d_out;

    init_h_kernel<<<128, dim3(64, 4)>>>(z, Wproj, bproj);
    transpose_wfc_kernel<<<dim3(VV / 32, EE / 32), dim3(32, 8)>>>(Wfc);

    int cur = 0;
    for (int t = 0; t < TT; t++) {
        gru_kernel<<<512, dim3(32, 8)>>>(Wih, bih, Whh, bhh, cur);
        logits_kernel<<<NVBLK, 128>>>(bfc, out, t, 1 - cur);
        argmax_embed_kernel<<<64, 128>>>(emb);
        cur = 1 - cur;
    }
}